// round 4
// baseline (speedup 1.0000x reference)
#include <cuda_runtime.h>
#include <cuda_bf16.h>
#include <stdint.h>

#define SQ 2048
#define DH 64
#define NH 16
#define NB 2
#define QROWS 16
#define JTILE 128
#define NJT (SQ / JTILE)
#define NTHREADS 256
#define INV_T 0.125f

// ---- smem layout (bytes) ----
// p' strips: 16 rows x pitch 2056 bf16 (pitch 2056*2 = 4112B -> LDSM conflict-free)
#define PS_B 4112
#define OFF_SSH 0
#define OFF_SSL (OFF_SSH + QROWS * PS_B)          // 65792
// K/V tiles: 128 rows x pitch 72 bf16 (144B rows)
#define PK_B 144
#define OFF_SKH (OFF_SSL + QROWS * PS_B)          // 131584
#define OFF_SKL (OFF_SKH + JTILE * PK_B)          // +18432
// Q tile: 16 rows x pitch 72 bf16
#define OFF_SQH (OFF_SKL + JTILE * PK_B)
#define OFF_SQL (OFF_SQH + QROWS * PK_B)
#define OFF_SUM (OFF_SQL + QROWS * PK_B)
#define OFF_INV (OFF_SUM + 64)
#define SMEM_BYTES (OFF_INV + 64)                 // 173184 B

// ---------------- PTX helpers ----------------

__device__ __forceinline__ uint32_t smem_u32(const void* p) {
    return (uint32_t)__cvta_generic_to_shared(p);
}

__device__ __forceinline__ void ldsm_x4(uint32_t addr, uint32_t* r) {
    asm volatile("ldmatrix.sync.aligned.m8n8.x4.shared.b16 {%0,%1,%2,%3}, [%4];"
                 : "=r"(r[0]), "=r"(r[1]), "=r"(r[2]), "=r"(r[3]) : "r"(addr));
}
__device__ __forceinline__ void ldsm_x2(uint32_t addr, uint32_t* r) {
    asm volatile("ldmatrix.sync.aligned.m8n8.x2.shared.b16 {%0,%1}, [%2];"
                 : "=r"(r[0]), "=r"(r[1]) : "r"(addr));
}
__device__ __forceinline__ void ldsm_x2t(uint32_t addr, uint32_t* r) {
    asm volatile("ldmatrix.sync.aligned.m8n8.x2.trans.shared.b16 {%0,%1}, [%2];"
                 : "=r"(r[0]), "=r"(r[1]) : "r"(addr));
}
__device__ __forceinline__ void mma_bf16(float* c, const uint32_t* a, const uint32_t* b) {
    asm volatile(
        "mma.sync.aligned.m16n8k16.row.col.f32.bf16.bf16.f32 "
        "{%0,%1,%2,%3}, {%4,%5,%6,%7}, {%8,%9}, {%0,%1,%2,%3};"
        : "+f"(c[0]), "+f"(c[1]), "+f"(c[2]), "+f"(c[3])
        : "r"(a[0]), "r"(a[1]), "r"(a[2]), "r"(a[3]), "r"(b[0]), "r"(b[1]));
}

__device__ __forceinline__ void split_bf(float x, uint16_t& h, uint16_t& l) {
    __nv_bfloat16 bh = __float2bfloat16(x);
    float r = x - __bfloat162float(bh);
    __nv_bfloat16 bl = __float2bfloat16(r);
    h = __bfloat16_as_ushort(bh);
    l = __bfloat16_as_ushort(bl);
}
__device__ __forceinline__ uint32_t pack2(uint16_t a, uint16_t b) {
    return (uint32_t)a | ((uint32_t)b << 16);
}
__device__ __forceinline__ float2 unpack2(uint32_t u) {
    __nv_bfloat162 b = *reinterpret_cast<__nv_bfloat162*>(&u);
    return __bfloat1622float2(b);
}

// split a float4 and store hi/lo uint2 into two planes at byte offset `off`
__device__ __forceinline__ void split_store4(char* sm, int offH, int offL, float4 f) {
    uint16_t h0, l0, h1, l1, h2, l2, h3, l3;
    split_bf(f.x, h0, l0); split_bf(f.y, h1, l1);
    split_bf(f.z, h2, l2); split_bf(f.w, h3, l3);
    uint2 H; H.x = pack2(h0, h1); H.y = pack2(h2, h3);
    uint2 L; L.x = pack2(l0, l1); L.y = pack2(l2, l3);
    *(uint2*)(sm + offH) = H;
    *(uint2*)(sm + offL) = L;
}

// ---------------- fused attention kernel ----------------

__global__ void __launch_bounds__(NTHREADS, 1)
sdpa_fused(const float* __restrict__ q, const float* __restrict__ k,
           const float* __restrict__ v, const int* __restrict__ mask,
           float* __restrict__ out, float* __restrict__ attn)
{
    extern __shared__ char sm[];
    float* sSum = (float*)(sm + OFF_SUM);
    float* sInv = (float*)(sm + OFF_INV);

    const int t    = threadIdx.x;
    const int lane = t & 31;
    const int w    = t >> 5;
    const int g    = lane >> 2;
    const int tg   = lane & 3;

    const int h  = blockIdx.y;
    const int b  = blockIdx.z;
    const int q0 = blockIdx.x * QROWS;
    const int bh = b * NH + h;

    const float* qg = q + ((size_t)bh * SQ + q0) * DH;
    const float* kg = k + (size_t)bh * SQ * DH;
    const float* vg = v + (size_t)bh * SQ * DH;
    const int*   mg = mask + ((size_t)b * SQ + q0) * SQ;
    float*       ag = attn + ((size_t)bh * SQ + q0) * SQ;
    float*       og = out  + ((size_t)bh * SQ + q0) * DH;

    if (t < QROWS) sSum[t] = 0.0f;

    // ---- load + split Q tile (16x64): exactly 256 float4s ----
    {
        int row = t >> 4, dc = t & 15;
        float4 f = *(const float4*)&qg[row * DH + dc * 4];
        split_store4(sm, OFF_SQH + row * PK_B + dc * 8,
                         OFF_SQL + row * PK_B + dc * 8, f);
    }

    // precomputed lane-dependent LDSM address parts
    const int aRow  = lane & 15;
    const int aColS = (lane >> 4) << 3;                 // 0 or 8
    const int bRowA = (w << 4) + (((lane >> 3) & 3) == 1 || lane >= 24 ? 0 : 0); // placeholder
    const int bRow  = (lane & 7);
    const int bColS = ((lane >> 3) & 1) << 3;           // 0/8 pattern for x2

    // ================= Pass A: p' = exp(mask(QK^T)/T) into smem, rowsums =================
    float rs0 = 0.0f, rs1 = 0.0f;

    for (int jt = 0; jt < NJT; ++jt) {
        __syncthreads();
        // load + split K tile 128x64
        #pragma unroll
        for (int i = 0; i < 8; ++i) {
            int lin = i * NTHREADS + t;
            int j = lin >> 4, dc = lin & 15;
            float4 f = *(const float4*)&kg[(jt * JTILE + j) * DH + dc * 4];
            split_store4(sm, OFF_SKH + j * PK_B + dc * 8,
                             OFF_SKL + j * PK_B + dc * 8, f);
        }
        __syncthreads();

        // 3 accumulator sets (independent dep-chains) x 2 nt
        float acc[3][2][4];
        #pragma unroll
        for (int s = 0; s < 3; ++s)
            #pragma unroll
            for (int nt = 0; nt < 2; ++nt)
                acc[s][nt][0] = acc[s][nt][1] = acc[s][nt][2] = acc[s][nt][3] = 0.0f;

        #pragma unroll
        for (int kc = 0; kc < 4; ++kc) {
            uint32_t Ah[4], Al[4];
            int aoff = aRow * PK_B + (kc * 16 + aColS) * 2;
            ldsm_x4(smem_u32(sm + OFF_SQH + aoff), Ah);
            ldsm_x4(smem_u32(sm + OFF_SQL + aoff), Al);

            uint32_t Bh0[2], Bl0[2], Bh1[2], Bl1[2];
            int boff0 = ((w << 4) + 0 + bRow) * PK_B + (kc * 16 + bColS) * 2;
            int boff1 = ((w << 4) + 8 + bRow) * PK_B + (kc * 16 + bColS) * 2;
            ldsm_x2(smem_u32(sm + OFF_SKH + boff0), Bh0);
            ldsm_x2(smem_u32(sm + OFF_SKL + boff0), Bl0);
            ldsm_x2(smem_u32(sm + OFF_SKH + boff1), Bh1);
            ldsm_x2(smem_u32(sm + OFF_SKL + boff1), Bl1);

            mma_bf16(acc[0][0], Ah, Bh0);
            mma_bf16(acc[0][1], Ah, Bh1);
            mma_bf16(acc[1][0], Ah, Bl0);
            mma_bf16(acc[1][1], Ah, Bl1);
            mma_bf16(acc[2][0], Al, Bh0);
            mma_bf16(acc[2][1], Al, Bh1);
        }

        // epilogue: combine terms, mask, exp, split+store p', accumulate rowsums
        #pragma unroll
        for (int nt = 0; nt < 2; ++nt) {
            int jl = jt * JTILE + (w << 4) + nt * 8 + 2 * tg;   // global j of c0
            float s00 = (acc[0][nt][0] + acc[1][nt][0]) + acc[2][nt][0];
            float s01 = (acc[0][nt][1] + acc[1][nt][1]) + acc[2][nt][1];
            float s10 = (acc[0][nt][2] + acc[1][nt][2]) + acc[2][nt][2];
            float s11 = (acc[0][nt][3] + acc[1][nt][3]) + acc[2][nt][3];
            int2 m0 = *(const int2*)&mg[g * SQ + jl];
            int2 m1 = *(const int2*)&mg[(g + 8) * SQ + jl];
            float e00 = m0.x ? __expf(s00 * INV_T) : 0.0f;
            float e01 = m0.y ? __expf(s01 * INV_T) : 0.0f;
            float e10 = m1.x ? __expf(s10 * INV_T) : 0.0f;
            float e11 = m1.y ? __expf(s11 * INV_T) : 0.0f;
            rs0 += e00 + e01;
            rs1 += e10 + e11;

            uint16_t h0, l0, h1, l1;
            split_bf(e00, h0, l0); split_bf(e01, h1, l1);
            *(uint32_t*)(sm + OFF_SSH + g * PS_B + jl * 2) = pack2(h0, h1);
            *(uint32_t*)(sm + OFF_SSL + g * PS_B + jl * 2) = pack2(l0, l1);
            split_bf(e10, h0, l0); split_bf(e11, h1, l1);
            *(uint32_t*)(sm + OFF_SSH + (g + 8) * PS_B + jl * 2) = pack2(h0, h1);
            *(uint32_t*)(sm + OFF_SSL + (g + 8) * PS_B + jl * 2) = pack2(l0, l1);
        }
    }

    // rowsum reduce: tg-group, then across warps
    rs0 += __shfl_xor_sync(0xffffffffu, rs0, 1);
    rs0 += __shfl_xor_sync(0xffffffffu, rs0, 2);
    rs1 += __shfl_xor_sync(0xffffffffu, rs1, 1);
    rs1 += __shfl_xor_sync(0xffffffffu, rs1, 2);
    if (tg == 0) {
        atomicAdd(&sSum[g], rs0);
        atomicAdd(&sSum[g + 8], rs1);
    }
    __syncthreads();
    if (t < QROWS) sInv[t] = 1.0f / sSum[t];

    // ================= Pass B: attn = p'*inv (write), out = P @ V =================
    float oacc[8][4];
    #pragma unroll
    for (int nt = 0; nt < 8; ++nt)
        oacc[nt][0] = oacc[nt][1] = oacc[nt][2] = oacc[nt][3] = 0.0f;

    for (int jt = 0; jt < NJT; ++jt) {
        __syncthreads();
        // load + split V tile 128x64 (same buffers as K)
        #pragma unroll
        for (int i = 0; i < 8; ++i) {
            int lin = i * NTHREADS + t;
            int j = lin >> 4, dc = lin & 15;
            float4 f = *(const float4*)&vg[(jt * JTILE + j) * DH + dc * 4];
            split_store4(sm, OFF_SKH + j * PK_B + dc * 8,
                             OFF_SKL + j * PK_B + dc * 8, f);
        }
        __syncthreads();

        // write normalized attn for this jt range (16 rows x 128 j)
        #pragma unroll
        for (int i = 0; i < 2; ++i) {
            int lin = i * NTHREADS + t;        // 0..511
            int row = lin >> 5;
            int jl  = jt * JTILE + (lin & 31) * 4;
            uint2 H = *(const uint2*)(sm + OFF_SSH + row * PS_B + jl * 2);
            uint2 L = *(const uint2*)(sm + OFF_SSL + row * PS_B + jl * 2);
            float2 h01 = unpack2(H.x), h23 = unpack2(H.y);
            float2 l01 = unpack2(L.x), l23 = unpack2(L.y);
            float iv = sInv[row];
            float4 o;
            o.x = (h01.x + l01.x) * iv;
            o.y = (h01.y + l01.y) * iv;
            o.z = (h23.x + l23.x) * iv;
            o.w = (h23.y + l23.y) * iv;
            *(float4*)&ag[row * SQ + jl] = o;
        }

        // PV: warp w handles k(j)-chunk [jt*128 + w*16, +16)
        uint32_t Ph[4], Pl[4];
        int poff = aRow * PS_B + (jt * JTILE + (w << 4) + aColS) * 2;
        ldsm_x4(smem_u32(sm + OFF_SSH + poff), Ph);
        ldsm_x4(smem_u32(sm + OFF_SSL + poff), Pl);

        #pragma unroll
        for (int nt = 0; nt < 8; ++nt) {
            uint32_t Bh[2], Bl[2];
            int voff = ((w << 4) + aRow) * PK_B + nt * 16;
            ldsm_x2t(smem_u32(sm + OFF_SKH + voff), Bh);
            ldsm_x2t(smem_u32(sm + OFF_SKL + voff), Bl);
            mma_bf16(oacc[nt], Ph, Bh);
            mma_bf16(oacc[nt], Ph, Bl);
            mma_bf16(oacc[nt], Pl, Bh);
        }
    }

    // cross-warp reduce of oacc via smem scratch (reuse K/V region)
    __syncthreads();
    float* scratch = (float*)(sm + OFF_SKH);   // 8 * 1024 floats = 32KB
    #pragma unroll
    for (int nt = 0; nt < 8; ++nt) {
        int col = nt * 8 + 2 * tg;
        *(float2*)&scratch[w * 1024 + g * 64 + col] =
            make_float2(oacc[nt][0], oacc[nt][1]);
        *(float2*)&scratch[w * 1024 + (g + 8) * 64 + col] =
            make_float2(oacc[nt][2], oacc[nt][3]);
    }
    __syncthreads();

    #pragma unroll
    for (int i = 0; i < 4; ++i) {
        int lin = i * NTHREADS + t;            // 0..1023
        int row = lin >> 6;
        float s = 0.0f;
        #pragma unroll
        for (int w2 = 0; w2 < 8; ++w2) s += scratch[w2 * 1024 + lin];
        og[lin] = s * sInv[row];
    }
}

// ---------------- launch ----------------

extern "C" void kernel_launch(void* const* d_in, const int* in_sizes, int n_in,
                              void* d_out, int out_size)
{
    const float* q    = (const float*)d_in[0];
    const float* k    = (const float*)d_in[1];
    const float* v    = (const float*)d_in[2];
    const int*   mask = (const int*)d_in[3];

    float* out  = (float*)d_out;
    float* attn = out + (size_t)NB * NH * SQ * DH;   // tuple order: (output, attn)

    cudaFuncSetAttribute(sdpa_fused, cudaFuncAttributeMaxDynamicSharedMemorySize,
                         SMEM_BYTES);

    dim3 grid(SQ / QROWS, NH, NB);
    sdpa_fused<<<grid, NTHREADS, SMEM_BYTES>>>(q, k, v, mask, out, attn);
}

// round 7
// speedup vs baseline: 1.6029x; 1.6029x over previous
#include <cuda_runtime.h>
#include <cuda_bf16.h>
#include <stdint.h>

#define SQ 2048
#define DH 64
#define NH 16
#define NB 2
#define INV_T 0.125f

__device__ float g_rowsum[NB * NH * SQ];

// ---------------- PTX helpers ----------------

__device__ __forceinline__ uint32_t smem_u32(const void* p) {
    return (uint32_t)__cvta_generic_to_shared(p);
}
__device__ __forceinline__ void ldsm_x4(uint32_t addr, uint32_t* r) {
    asm volatile("ldmatrix.sync.aligned.m8n8.x4.shared.b16 {%0,%1,%2,%3}, [%4];"
                 : "=r"(r[0]), "=r"(r[1]), "=r"(r[2]), "=r"(r[3]) : "r"(addr));
}
__device__ __forceinline__ void ldsm_x4t(uint32_t addr, uint32_t* r) {
    asm volatile("ldmatrix.sync.aligned.m8n8.x4.trans.shared.b16 {%0,%1,%2,%3}, [%4];"
                 : "=r"(r[0]), "=r"(r[1]), "=r"(r[2]), "=r"(r[3]) : "r"(addr));
}
__device__ __forceinline__ void mma_bf16(float* c, const uint32_t* a, const uint32_t* b) {
    asm volatile(
        "mma.sync.aligned.m16n8k16.row.col.f32.bf16.bf16.f32 "
        "{%0,%1,%2,%3}, {%4,%5,%6,%7}, {%8,%9}, {%0,%1,%2,%3};"
        : "+f"(c[0]), "+f"(c[1]), "+f"(c[2]), "+f"(c[3])
        : "r"(a[0]), "r"(a[1]), "r"(a[2]), "r"(a[3]), "r"(b[0]), "r"(b[1]));
}

__device__ __forceinline__ void split_bf(float x, uint16_t& h, uint16_t& l) {
    __nv_bfloat16 bh = __float2bfloat16(x);
    float r = x - __bfloat162float(bh);
    __nv_bfloat16 bl = __float2bfloat16(r);
    h = __bfloat16_as_ushort(bh);
    l = __bfloat16_as_ushort(bl);
}
__device__ __forceinline__ uint32_t pack2(uint16_t a, uint16_t b) {
    return (uint32_t)a | ((uint32_t)b << 16);
}
__device__ __forceinline__ void split_store4(char* smp, int offH, int offL, float4 f) {
    uint16_t h0, l0, h1, l1, h2, l2, h3, l3;
    split_bf(f.x, h0, l0); split_bf(f.y, h1, l1);
    split_bf(f.z, h2, l2); split_bf(f.w, h3, l3);
    uint2 H; H.x = pack2(h0, h1); H.y = pack2(h2, h3);
    uint2 L; L.x = pack2(l0, l1); L.y = pack2(l2, l3);
    *(uint2*)(smp + offH) = H;
    *(uint2*)(smp + offL) = L;
}

// ================= Kernel 1: p' = exp(mask(QK^T/T)) -> gmem, row sums =================
// CTA: 64 q-rows, 256 thr (4 M-warps x 2 N-warps), j-tiles of 128.
// smem: Qh/Ql 64x72 bf16, Kh/Kl 128x72 bf16, sums.
#define PQ_B 144                              // 72 bf16 pitch in bytes
#define K1_QH 0
#define K1_QL (64 * PQ_B)                     // 9216
#define K1_KH (2 * 64 * PQ_B)                 // 18432
#define K1_KL (K1_KH + 128 * PQ_B)            // 36864
#define K1_SUM (K1_KL + 128 * PQ_B)           // 55296
#define K1_SMEM (K1_SUM + 256)                // 55552

__global__ void __launch_bounds__(256, 2)
k1_qk(const float* __restrict__ q, const float* __restrict__ k,
      const int* __restrict__ mask, float* __restrict__ attn)
{
    extern __shared__ char sm[];
    float* sSum = (float*)(sm + K1_SUM);

    const int t = threadIdx.x;
    const int lane = t & 31, w = t >> 5;
    const int g = lane >> 2, tg = lane & 3;
    const int wm = w >> 1, wn = w & 1;

    const int h  = blockIdx.y;
    const int b  = blockIdx.z;
    const int q0 = blockIdx.x * 64;
    const int bh = b * NH + h;

    const float* qg = q + ((size_t)bh * SQ + q0) * DH;
    const float* kg = k + (size_t)bh * SQ * DH;
    const int*   mg = mask + ((size_t)b * SQ + q0) * SQ;
    float*       ag = attn + ((size_t)bh * SQ + q0) * SQ;

    // stage Q (64x64): 1024 float4 / 256 thr = 4 each
    #pragma unroll
    for (int i = 0; i < 4; ++i) {
        int lin = i * 256 + t;
        int r = lin >> 4, dc = lin & 15;
        float4 f = *(const float4*)&qg[r * DH + dc * 4];
        split_store4(sm, K1_QH + r * PQ_B + dc * 8, K1_QL + r * PQ_B + dc * 8, f);
    }
    if (t < 64) sSum[t] = 0.0f;

    // LDSM address components
    const int aRow = wm * 16 + (lane & 15);
    const int aCol = ((lane >> 4) << 3);
    const int bRow = ((lane >> 4) << 3) + (lane & 7);       // + base_n
    const int bCol = ((lane >> 3) & 1) << 3;

    const int rl0 = wm * 16 + g, rl1 = rl0 + 8;
    float rs0 = 0.0f, rs1 = 0.0f;

    for (int jt = 0; jt < 16; ++jt) {
        __syncthreads();
        // stage K tile 128x64: 2048 float4 / 256 = 8 each
        #pragma unroll
        for (int i = 0; i < 8; ++i) {
            int lin = i * 256 + t;
            int j = lin >> 4, dc = lin & 15;
            float4 f = *(const float4*)&kg[(jt * 128 + j) * DH + dc * 4];
            split_store4(sm, K1_KH + j * PQ_B + dc * 8, K1_KL + j * PQ_B + dc * 8, f);
        }
        __syncthreads();

        float acc[8][4];
        #pragma unroll
        for (int nt = 0; nt < 8; ++nt)
            acc[nt][0] = acc[nt][1] = acc[nt][2] = acc[nt][3] = 0.0f;

        #pragma unroll
        for (int kc = 0; kc < 4; ++kc) {
            uint32_t Ah[4], Al[4];
            int aoff = aRow * PQ_B + (kc * 16 + aCol) * 2;
            ldsm_x4(smem_u32(sm + K1_QH + aoff), Ah);
            ldsm_x4(smem_u32(sm + K1_QL + aoff), Al);

            #pragma unroll
            for (int np = 0; np < 4; ++np) {
                uint32_t Bh[4], Bl[4];
                int boff = (wn * 64 + np * 16 + bRow) * PQ_B + (kc * 16 + bCol) * 2;
                ldsm_x4(smem_u32(sm + K1_KH + boff), Bh);
                ldsm_x4(smem_u32(sm + K1_KL + boff), Bl);
                mma_bf16(acc[np * 2],     Ah, Bh);
                mma_bf16(acc[np * 2],     Ah, Bl);
                mma_bf16(acc[np * 2],     Al, Bh);
                mma_bf16(acc[np * 2 + 1], Ah, Bh + 2);
                mma_bf16(acc[np * 2 + 1], Ah, Bl + 2);
                mma_bf16(acc[np * 2 + 1], Al, Bh + 2);
            }
        }

        // epilogue: mask, scale, exp, store p', rowsums
        #pragma unroll
        for (int nt = 0; nt < 8; ++nt) {
            int jc = jt * 128 + wn * 64 + nt * 8 + 2 * tg;
            int2 m0 = *(const int2*)&mg[rl0 * SQ + jc];
            int2 m1 = *(const int2*)&mg[rl1 * SQ + jc];
            float e00 = m0.x ? __expf(acc[nt][0] * INV_T) : 0.0f;
            float e01 = m0.y ? __expf(acc[nt][1] * INV_T) : 0.0f;
            float e10 = m1.x ? __expf(acc[nt][2] * INV_T) : 0.0f;
            float e11 = m1.y ? __expf(acc[nt][3] * INV_T) : 0.0f;
            *(float2*)&ag[rl0 * SQ + jc] = make_float2(e00, e01);
            *(float2*)&ag[rl1 * SQ + jc] = make_float2(e10, e11);
            rs0 += e00 + e01;
            rs1 += e10 + e11;
        }
    }

    rs0 += __shfl_xor_sync(0xffffffffu, rs0, 1);
    rs0 += __shfl_xor_sync(0xffffffffu, rs0, 2);
    rs1 += __shfl_xor_sync(0xffffffffu, rs1, 1);
    rs1 += __shfl_xor_sync(0xffffffffu, rs1, 2);
    if (tg == 0) {
        atomicAdd(&sSum[rl0], rs0);
        atomicAdd(&sSum[rl1], rs1);
    }
    __syncthreads();
    if (t < 64) g_rowsum[(size_t)bh * SQ + q0 + t] = sSum[t];
}

// ================= Kernel 2: attn = p'/sum (in place), out = attn @ V =================
// CTA: 64 q-rows, 256 thr (4 M-warps x 2 D-warps), j-tiles of 64.
// smem: Ph/Pl 64x72 bf16, Vh/Vl 64x72 bf16, inv.
#define K2_PH 0
#define K2_PL (64 * PQ_B)
#define K2_VH (2 * 64 * PQ_B)
#define K2_VL (3 * 64 * PQ_B)
#define K2_INV (4 * 64 * PQ_B)                // 36864
#define K2_SMEM (K2_INV + 256)

__global__ void __launch_bounds__(256, 2)
k2_pv(const float* __restrict__ v, float* __restrict__ attn, float* __restrict__ out)
{
    extern __shared__ char sm[];
    float* sInv = (float*)(sm + K2_INV);

    const int t = threadIdx.x;
    const int lane = t & 31, w = t >> 5;
    const int g = lane >> 2, tg = lane & 3;
    const int wm = w >> 1, wn = w & 1;

    const int h  = blockIdx.y;
    const int b  = blockIdx.z;
    const int q0 = blockIdx.x * 64;
    const int bh = b * NH + h;

    const float* vg = v + (size_t)bh * SQ * DH;
    float*       ag = attn + ((size_t)bh * SQ + q0) * SQ;
    float*       og = out  + ((size_t)bh * SQ + q0) * DH;

    if (t < 64) sInv[t] = 1.0f / g_rowsum[(size_t)bh * SQ + q0 + t];

    const int aRow = wm * 16 + (lane & 15);
    const int aCol = ((lane >> 4) << 3);
    const int vRow = lane & 15;                 // + base_k
    const int vCol = ((lane >> 4) << 4);        // bytes

    float acc[4][4];
    #pragma unroll
    for (int nt = 0; nt < 4; ++nt)
        acc[nt][0] = acc[nt][1] = acc[nt][2] = acc[nt][3] = 0.0f;

    for (int jt = 0; jt < 32; ++jt) {
        __syncthreads();
        // stage P tile 64x64: normalize, write final attn, split to smem
        #pragma unroll
        for (int i = 0; i < 4; ++i) {
            int lin = i * 256 + t;
            int r = lin >> 4, jg = lin & 15;
            float4 x = *(float4*)&ag[r * SQ + jt * 64 + jg * 4];
            float iv = sInv[r];
            x.x *= iv; x.y *= iv; x.z *= iv; x.w *= iv;
            *(float4*)&ag[r * SQ + jt * 64 + jg * 4] = x;
            split_store4(sm, K2_PH + r * PQ_B + jg * 8, K2_PL + r * PQ_B + jg * 8, x);
        }
        // stage V tile 64x64
        #pragma unroll
        for (int i = 0; i < 4; ++i) {
            int lin = i * 256 + t;
            int jl = lin >> 4, dc = lin & 15;
            float4 f = *(const float4*)&vg[(jt * 64 + jl) * DH + dc * 4];
            split_store4(sm, K2_VH + jl * PQ_B + dc * 8, K2_VL + jl * PQ_B + dc * 8, f);
        }
        __syncthreads();

        #pragma unroll
        for (int kc = 0; kc < 4; ++kc) {
            uint32_t Ah[4], Al[4];
            int aoff = aRow * PQ_B + (kc * 16 + aCol) * 2;
            ldsm_x4(smem_u32(sm + K2_PH + aoff), Ah);
            ldsm_x4(smem_u32(sm + K2_PL + aoff), Al);

            #pragma unroll
            for (int np = 0; np < 2; ++np) {
                uint32_t Bh[4], Bl[4];
                // B = V^T fragment: rows j(=k) kc*16.., cols d = wn*32+np*16..
                int voff = (kc * 16 + vRow) * PQ_B + (wn * 32 + np * 16) * 2 + vCol;
                ldsm_x4t(smem_u32(sm + K2_VH + voff), Bh);
                ldsm_x4t(smem_u32(sm + K2_VL + voff), Bl);
                mma_bf16(acc[np * 2],     Ah, Bh);
                mma_bf16(acc[np * 2],     Ah, Bl);
                mma_bf16(acc[np * 2],     Al, Bh);
                mma_bf16(acc[np * 2 + 1], Ah, Bh + 2);
                mma_bf16(acc[np * 2 + 1], Ah, Bl + 2);
                mma_bf16(acc[np * 2 + 1], Al, Bh + 2);
            }
        }
    }

    // write output: P was pre-normalized, no final scale
    const int rl0 = wm * 16 + g, rl1 = rl0 + 8;
    #pragma unroll
    for (int nt = 0; nt < 4; ++nt) {
        int dc = wn * 32 + nt * 8 + 2 * tg;
        *(float2*)&og[rl0 * DH + dc] = make_float2(acc[nt][0], acc[nt][1]);
        *(float2*)&og[rl1 * DH + dc] = make_float2(acc[nt][2], acc[nt][3]);
    }
}

// ---------------- launch ----------------

extern "C" void kernel_launch(void* const* d_in, const int* in_sizes, int n_in,
                              void* d_out, int out_size)
{
    const float* q    = (const float*)d_in[0];
    const float* k    = (const float*)d_in[1];
    const float* v    = (const float*)d_in[2];
    const int*   mask = (const int*)d_in[3];

    float* out  = (float*)d_out;
    float* attn = out + (size_t)NB * NH * SQ * DH;   // tuple order: (output, attn)

    cudaFuncSetAttribute(k1_qk, cudaFuncAttributeMaxDynamicSharedMemorySize, K1_SMEM);
    cudaFuncSetAttribute(k2_pv, cudaFuncAttributeMaxDynamicSharedMemorySize, K2_SMEM);

    dim3 grid(SQ / 64, NH, NB);
    k1_qk<<<grid, 256, K1_SMEM>>>(q, k, mask, attn);
    k2_pv<<<grid, 256, K2_SMEM>>>(v, attn, out);
}

// round 9
// speedup vs baseline: 2.5096x; 1.5656x over previous
#include <cuda_runtime.h>
#include <cuda_bf16.h>
#include <stdint.h>

#define SQ 2048
#define DH 64
#define NH 16
#define NB 2
#define INV_T 0.125f
#define N_ELEM (NB * NH * SQ * DH)   // 4194304

__device__ float g_rowsum[NB * NH * SQ];
// pre-split bf16 hi/lo planes
__device__ unsigned short gQh[N_ELEM], gQl[N_ELEM];
__device__ unsigned short gKh[N_ELEM], gKl[N_ELEM];
__device__ unsigned short gVh[N_ELEM], gVl[N_ELEM];

// ---------------- PTX helpers ----------------

__device__ __forceinline__ uint32_t smem_u32(const void* p) {
    return (uint32_t)__cvta_generic_to_shared(p);
}
__device__ __forceinline__ void ldsm_x4(uint32_t addr, uint32_t* r) {
    asm volatile("ldmatrix.sync.aligned.m8n8.x4.shared.b16 {%0,%1,%2,%3}, [%4];"
                 : "=r"(r[0]), "=r"(r[1]), "=r"(r[2]), "=r"(r[3]) : "r"(addr));
}
__device__ __forceinline__ void ldsm_x4t(uint32_t addr, uint32_t* r) {
    asm volatile("ldmatrix.sync.aligned.m8n8.x4.trans.shared.b16 {%0,%1,%2,%3}, [%4];"
                 : "=r"(r[0]), "=r"(r[1]), "=r"(r[2]), "=r"(r[3]) : "r"(addr));
}
__device__ __forceinline__ void mma_bf16(float* c, const uint32_t* a, const uint32_t* b) {
    asm volatile(
        "mma.sync.aligned.m16n8k16.row.col.f32.bf16.bf16.f32 "
        "{%0,%1,%2,%3}, {%4,%5,%6,%7}, {%8,%9}, {%0,%1,%2,%3};"
        : "+f"(c[0]), "+f"(c[1]), "+f"(c[2]), "+f"(c[3])
        : "r"(a[0]), "r"(a[1]), "r"(a[2]), "r"(a[3]), "r"(b[0]), "r"(b[1]));
}
__device__ __forceinline__ void cp16(uint32_t s, const void* g) {
    asm volatile("cp.async.cg.shared.global [%0], [%1], 16;" :: "r"(s), "l"(g));
}
#define CP_COMMIT asm volatile("cp.async.commit_group;")
#define CP_WAIT1  asm volatile("cp.async.wait_group 1;")
#define CP_WAIT0  asm volatile("cp.async.wait_group 0;")

__device__ __forceinline__ void split_bf(float x, uint16_t& h, uint16_t& l) {
    __nv_bfloat16 bh = __float2bfloat16(x);
    float r = x - __bfloat162float(bh);
    __nv_bfloat16 bl = __float2bfloat16(r);
    h = __bfloat16_as_ushort(bh);
    l = __bfloat16_as_ushort(bl);
}
__device__ __forceinline__ uint32_t pack2(uint16_t a, uint16_t b) {
    return (uint32_t)a | ((uint32_t)b << 16);
}

// ================= Kernel 0: split Q/K/V into bf16 hi/lo planes =================
__global__ void __launch_bounds__(256)
prep(const float* __restrict__ q, const float* __restrict__ k, const float* __restrict__ v)
{
    int id = blockIdx.x * 256 + threadIdx.x;          // 0 .. 3*N/4-1
    int tsel = id / (N_ELEM / 4);
    int i4   = id % (N_ELEM / 4);
    const float* src = (tsel == 0) ? q : (tsel == 1) ? k : v;
    unsigned short* dh = (tsel == 0) ? gQh : (tsel == 1) ? gKh : gVh;
    unsigned short* dl = (tsel == 0) ? gQl : (tsel == 1) ? gKl : gVl;

    float4 f = ((const float4*)src)[i4];
    uint16_t h0, l0, h1, l1, h2, l2, h3, l3;
    split_bf(f.x, h0, l0); split_bf(f.y, h1, l1);
    split_bf(f.z, h2, l2); split_bf(f.w, h3, l3);
    uint2 H; H.x = pack2(h0, h1); H.y = pack2(h2, h3);
    uint2 L; L.x = pack2(l0, l1); L.y = pack2(l2, l3);
    ((uint2*)dh)[i4] = H;
    ((uint2*)dl)[i4] = L;
}

// ================= Kernel 1: p' = exp(mask(QK^T/T)) -> gmem, row sums =================
// 64 q-rows/CTA, 256 thr (4 M-warps x 2 N-warps), j-tiles of 128, cp.async double-buffer.
#define PQ_B 144                               // 72 bf16 pitch (bytes)
#define K1_QH 0
#define K1_QL (64 * PQ_B)                      // 9216
#define K1_KBUF 18432                          // 2 buffers of (KH+KL) = 36864 each
#define K1_KSZ  36864
#define K1_SUM (K1_KBUF + 2 * K1_KSZ)          // 92160
#define K1_SMEM (K1_SUM + 256)

__global__ void __launch_bounds__(256, 2)
k1_qk(const int* __restrict__ mask, float* __restrict__ attn)
{
    extern __shared__ char sm[];
    float* sSum = (float*)(sm + K1_SUM);

    const int t = threadIdx.x;
    const int lane = t & 31, w = t >> 5;
    const int g = lane >> 2, tg = lane & 3;
    const int wm = w >> 1, wn = w & 1;

    const int h  = blockIdx.y;
    const int b  = blockIdx.z;
    const int q0 = blockIdx.x * 64;
    const int bh = b * NH + h;

    const int* mg = mask + ((size_t)b * SQ + q0) * SQ;
    float*     ag = attn + ((size_t)bh * SQ + q0) * SQ;

    const size_t qbase = ((size_t)bh * SQ + q0) * DH;   // ushort index
    const size_t kbase = (size_t)bh * SQ * DH;

    // prologue: stage Q planes (1024 chunks) + K tile 0 (2048 chunks)
    #pragma unroll
    for (int i = 0; i < 4; ++i) {
        int lin = i * 256 + t;
        int plane = lin >> 9, row = (lin >> 3) & 63, c = lin & 7;
        const unsigned short* src = (plane ? gQl : gQh) + qbase + (size_t)row * DH + c * 8;
        cp16(smem_u32(sm + (plane ? K1_QL : K1_QH) + row * PQ_B + c * 16), src);
    }
    #pragma unroll
    for (int i = 0; i < 8; ++i) {
        int lin = i * 256 + t;
        int plane = lin >> 10, row = (lin >> 3) & 127, c = lin & 7;
        const unsigned short* src = (plane ? gKl : gKh) + kbase + (size_t)row * DH + c * 8;
        cp16(smem_u32(sm + K1_KBUF + plane * (K1_KSZ / 2) + row * PQ_B + c * 16), src);
    }
    CP_COMMIT;
    if (t < 64) sSum[t] = 0.0f;

    const int aRow = wm * 16 + (lane & 15);
    const int aCol = ((lane >> 4) << 3);
    const int bRow = ((lane >> 4) << 3) + (lane & 7);
    const int bCol = ((lane >> 3) & 1) << 3;
    const int rl0 = wm * 16 + g, rl1 = rl0 + 8;
    float rs0 = 0.0f, rs1 = 0.0f;

    for (int jt = 0; jt < 16; ++jt) {
        __syncthreads();     // compute jt-1 fully done -> safe to overwrite buf[(jt+1)&1]
        if (jt < 15) {
            char* kb = sm + K1_KBUF + ((jt + 1) & 1) * K1_KSZ;
            size_t kt = kbase + (size_t)(jt + 1) * 128 * DH;
            #pragma unroll
            for (int i = 0; i < 8; ++i) {
                int lin = i * 256 + t;
                int plane = lin >> 10, row = (lin >> 3) & 127, c = lin & 7;
                const unsigned short* src = (plane ? gKl : gKh) + kt + (size_t)row * DH + c * 8;
                cp16(smem_u32(kb + plane * (K1_KSZ / 2) + row * PQ_B + c * 16), src);
            }
            CP_COMMIT;
            CP_WAIT1;
        } else {
            CP_WAIT0;
        }
        __syncthreads();     // tile jt staged + visible

        const char* KB = sm + K1_KBUF + (jt & 1) * K1_KSZ;

        float acc[8][4];
        #pragma unroll
        for (int nt = 0; nt < 8; ++nt)
            acc[nt][0] = acc[nt][1] = acc[nt][2] = acc[nt][3] = 0.0f;

        #pragma unroll
        for (int kc = 0; kc < 4; ++kc) {
            uint32_t Ah[4], Al[4];
            int aoff = aRow * PQ_B + (kc * 16 + aCol) * 2;
            ldsm_x4(smem_u32(sm + K1_QH + aoff), Ah);
            ldsm_x4(smem_u32(sm + K1_QL + aoff), Al);

            #pragma unroll
            for (int np = 0; np < 4; ++np) {
                uint32_t Bh[4], Bl[4];
                int boff = (wn * 64 + np * 16 + bRow) * PQ_B + (kc * 16 + bCol) * 2;
                ldsm_x4(smem_u32(KB + boff), Bh);
                ldsm_x4(smem_u32(KB + (K1_KSZ / 2) + boff), Bl);
                mma_bf16(acc[np * 2],     Ah, Bh);
                mma_bf16(acc[np * 2],     Ah, Bl);
                mma_bf16(acc[np * 2],     Al, Bh);
                mma_bf16(acc[np * 2 + 1], Ah, Bh + 2);
                mma_bf16(acc[np * 2 + 1], Ah, Bl + 2);
                mma_bf16(acc[np * 2 + 1], Al, Bh + 2);
            }
        }

        #pragma unroll
        for (int nt = 0; nt < 8; ++nt) {
            int jc = jt * 128 + wn * 64 + nt * 8 + 2 * tg;
            int2 m0 = *(const int2*)&mg[rl0 * SQ + jc];
            int2 m1 = *(const int2*)&mg[rl1 * SQ + jc];
            float e00 = m0.x ? __expf(acc[nt][0] * INV_T) : 0.0f;
            float e01 = m0.y ? __expf(acc[nt][1] * INV_T) : 0.0f;
            float e10 = m1.x ? __expf(acc[nt][2] * INV_T) : 0.0f;
            float e11 = m1.y ? __expf(acc[nt][3] * INV_T) : 0.0f;
            *(float2*)&ag[rl0 * SQ + jc] = make_float2(e00, e01);
            *(float2*)&ag[rl1 * SQ + jc] = make_float2(e10, e11);
            rs0 += e00 + e01;
            rs1 += e10 + e11;
        }
    }

    rs0 += __shfl_xor_sync(0xffffffffu, rs0, 1);
    rs0 += __shfl_xor_sync(0xffffffffu, rs0, 2);
    rs1 += __shfl_xor_sync(0xffffffffu, rs1, 1);
    rs1 += __shfl_xor_sync(0xffffffffu, rs1, 2);
    if (tg == 0) {
        atomicAdd(&sSum[rl0], rs0);
        atomicAdd(&sSum[rl1], rs1);
    }
    __syncthreads();
    if (t < 64) g_rowsum[(size_t)bh * SQ + q0 + t] = sSum[t];
}

// ================= Kernel 2: attn = p'/sum (in place), out = attn @ V =================
// 64 q-rows/CTA, 256 thr (4 M x 2 D warps), j-tiles of 64, cp.async double-buffer.
#define K2_PH 0
#define K2_PL (64 * PQ_B)
#define K2_BUF (2 * 64 * PQ_B)                 // 18432; buffers: p' fp32 + VH + VL
#define PP_B 272                               // p' pitch bytes (68 floats)
#define K2_BSZ (64 * PP_B + 2 * 64 * PQ_B)     // 17408 + 18432 = 35840
#define K2_VOFF (64 * PP_B)                    // V planes offset inside buffer
#define K2_INV (K2_BUF + 2 * K2_BSZ)           // 90112
#define K2_SMEM (K2_INV + 256)

__global__ void __launch_bounds__(256, 2)
k2_pv(float* __restrict__ attn, float* __restrict__ out)
{
    extern __shared__ char sm[];
    float* sInv = (float*)(sm + K2_INV);

    const int t = threadIdx.x;
    const int lane = t & 31, w = t >> 5;
    const int g = lane >> 2, tg = lane & 3;
    const int wm = w >> 1, wn = w & 1;

    const int h  = blockIdx.y;
    const int b  = blockIdx.z;
    const int q0 = blockIdx.x * 64;
    const int bh = b * NH + h;

    float* ag = attn + ((size_t)bh * SQ + q0) * SQ;
    float* og = out  + ((size_t)bh * SQ + q0) * DH;
    const size_t vbase = (size_t)bh * SQ * DH;

    if (t < 64) sInv[t] = 1.0f / g_rowsum[(size_t)bh * SQ + q0 + t];

    // stage tile 0
    {
        char* bufp = sm + K2_BUF;
        #pragma unroll
        for (int i = 0; i < 4; ++i) {              // p' 1024 chunks
            int lin = i * 256 + t;
            int row = lin >> 4, c = lin & 15;
            cp16(smem_u32(bufp + row * PP_B + c * 16), &ag[(size_t)row * SQ + c * 4]);
        }
        #pragma unroll
        for (int i = 0; i < 4; ++i) {              // V planes 1024 chunks
            int lin = i * 256 + t;
            int plane = lin >> 9, row = (lin >> 3) & 63, c = lin & 7;
            const unsigned short* src = (plane ? gVl : gVh) + vbase + (size_t)row * DH + c * 8;
            cp16(smem_u32(bufp + K2_VOFF + plane * (64 * PQ_B) + row * PQ_B + c * 16), src);
        }
        CP_COMMIT;
    }

    const int aRow = wm * 16 + (lane & 15);
    const int aCol = ((lane >> 4) << 3);
    const int vRow = lane & 15;
    const int vCol = ((lane >> 4) << 4);

    float acc[4][4];
    #pragma unroll
    for (int nt = 0; nt < 4; ++nt)
        acc[nt][0] = acc[nt][1] = acc[nt][2] = acc[nt][3] = 0.0f;

    for (int jt = 0; jt < 32; ++jt) {
        __syncthreads();     // MMA jt-1 done: P planes + buf[(jt+1)&1] free
        if (jt < 31) {
            char* bufp = sm + K2_BUF + ((jt + 1) & 1) * K2_BSZ;
            int jn = (jt + 1) * 64;
            #pragma unroll
            for (int i = 0; i < 4; ++i) {
                int lin = i * 256 + t;
                int row = lin >> 4, c = lin & 15;
                cp16(smem_u32(bufp + row * PP_B + c * 16), &ag[(size_t)row * SQ + jn + c * 4]);
            }
            #pragma unroll
            for (int i = 0; i < 4; ++i) {
                int lin = i * 256 + t;
                int plane = lin >> 9, row = (lin >> 3) & 63, c = lin & 7;
                const unsigned short* src = (plane ? gVl : gVh) + vbase
                                          + (size_t)(jn + row) * DH + c * 8;
                cp16(smem_u32(bufp + K2_VOFF + plane * (64 * PQ_B) + row * PQ_B + c * 16), src);
            }
            CP_COMMIT;
            CP_WAIT1;
        } else {
            CP_WAIT0;
        }
        __syncthreads();     // tile jt staged

        char* BUF = sm + K2_BUF + (jt & 1) * K2_BSZ;

        // normalize p' -> write final attn + split to P planes
        #pragma unroll
        for (int i = 0; i < 4; ++i) {
            int lin = i * 256 + t;
            int row = lin >> 4, jg = lin & 15;
            float4 x = *(const float4*)(BUF + row * PP_B + jg * 16);
            float iv = sInv[row];
            x.x *= iv; x.y *= iv; x.z *= iv; x.w *= iv;
            *(float4*)&ag[(size_t)row * SQ + jt * 64 + jg * 4] = x;
            uint16_t h0, l0, h1, l1, h2, l2, h3, l3;
            split_bf(x.x, h0, l0); split_bf(x.y, h1, l1);
            split_bf(x.z, h2, l2); split_bf(x.w, h3, l3);
            uint2 H; H.x = pack2(h0, h1); H.y = pack2(h2, h3);
            uint2 L; L.x = pack2(l0, l1); L.y = pack2(l2, l3);
            *(uint2*)(sm + K2_PH + row * PQ_B + jg * 8) = H;
            *(uint2*)(sm + K2_PL + row * PQ_B + jg * 8) = L;
        }
        __syncthreads();     // P planes ready

        const char* VH = BUF + K2_VOFF;
        const char* VL = VH + 64 * PQ_B;

        #pragma unroll
        for (int kc = 0; kc < 4; ++kc) {
            uint32_t Ah[4], Al[4];
            int aoff = aRow * PQ_B + (kc * 16 + aCol) * 2;
            ldsm_x4(smem_u32(sm + K2_PH + aoff), Ah);
            ldsm_x4(smem_u32(sm + K2_PL + aoff), Al);

            #pragma unroll
            for (int np = 0; np < 2; ++np) {
                uint32_t Bh[4], Bl[4];
                int voff = (kc * 16 + vRow) * PQ_B + (wn * 32 + np * 16) * 2 + vCol;
                ldsm_x4t(smem_u32(VH + voff), Bh);
                ldsm_x4t(smem_u32(VL + voff), Bl);
                mma_bf16(acc[np * 2],     Ah, Bh);
                mma_bf16(acc[np * 2],     Ah, Bl);
                mma_bf16(acc[np * 2],     Al, Bh);
                mma_bf16(acc[np * 2 + 1], Ah, Bh + 2);
                mma_bf16(acc[np * 2 + 1], Ah, Bl + 2);
                mma_bf16(acc[np * 2 + 1], Al, Bh + 2);
            }
        }
    }

    const int rl0 = wm * 16 + g, rl1 = rl0 + 8;
    #pragma unroll
    for (int nt = 0; nt < 4; ++nt) {
        int dc = wn * 32 + nt * 8 + 2 * tg;
        *(float2*)&og[rl0 * DH + dc] = make_float2(acc[nt][0], acc[nt][1]);
        *(float2*)&og[rl1 * DH + dc] = make_float2(acc[nt][2], acc[nt][3]);
    }
}

// ---------------- launch ----------------

extern "C" void kernel_launch(void* const* d_in, const int* in_sizes, int n_in,
                              void* d_out, int out_size)
{
    const float* q    = (const float*)d_in[0];
    const float* k    = (const float*)d_in[1];
    const float* v    = (const float*)d_in[2];
    const int*   mask = (const int*)d_in[3];

    float* out  = (float*)d_out;
    float* attn = out + (size_t)NB * NH * SQ * DH;   // tuple order: (output, attn)

    cudaFuncSetAttribute(k1_qk, cudaFuncAttributeMaxDynamicSharedMemorySize, K1_SMEM);
    cudaFuncSetAttribute(k2_pv, cudaFuncAttributeMaxDynamicSharedMemorySize, K2_SMEM);

    const int prep_blocks = 3 * (N_ELEM / 4) / 256;
    prep<<<prep_blocks, 256>>>(q, k, v);
    dim3 grid(SQ / 64, NH, NB);
    k1_qk<<<grid, 256, K1_SMEM>>>(mask, attn);
    k2_pv<<<grid, 256, K2_SMEM>>>(attn, out);
}